// round 13
// baseline (speedup 1.0000x reference)
#include <cuda_runtime.h>
#include <cuda_fp16.h>
#include <math.h>
#include <cstdint>

#define B_ 8
#define S_ 1024
#define D_ 768
#define H_ 3072
#define T_ (B_*S_)

typedef long long ll;

// ---------------- scratch: fp16 operands -------------------------------------
static __device__ __half g_yh  [T_*D_];
static __device__ __half g_y1h [T_*D_];
static __device__ __half g_qh  [T_*H_];
static __device__ __half g_kh  [T_*H_];
static __device__ __half g_vTh [B_*H_*S_];
static __device__ __half g_sh  [B_*S_*S_];
static __device__ __half g_avh [T_*H_];
static __device__ __half g_h1h [T_*H_];
static __device__ __half g_wqt [H_*D_];
static __device__ __half g_wkt [H_*D_];
static __device__ __half g_wvt [H_*D_];
static __device__ __half g_wot [D_*H_];
static __device__ __half g_w1t [H_*D_];
static __device__ __half g_w2t [D_*H_];
// fp32 scratch
static __device__ float g_pe [S_*D_];
static __device__ float g_y  [T_*D_];
static __device__ float g_s  [B_*S_*S_];
static __device__ float g_ao [T_*D_];
static __device__ float g_y1 [T_*D_];
static __device__ float g_f  [T_*D_];
static __device__ double g_part[B_*128*2];
static __device__ double g_stats[B_*2];

// ------------------------------------------------------------- helpers ------
__device__ __forceinline__ uint32_t smem_u32(const void* p) {
    uint32_t a;
    asm("{ .reg .u64 t; cvta.to.shared.u64 t, %1; cvt.u32.u64 %0, t; }" : "=r"(a) : "l"(p));
    return a;
}
#define CP16(dst, src) \
    asm volatile("cp.async.cg.shared.global [%0], [%1], 16;" :: "r"(dst), "l"(src) : "memory")
#define CP_COMMIT() asm volatile("cp.async.commit_group;" ::: "memory")
#define CP_WAIT0()  asm volatile("cp.async.wait_group 0;" ::: "memory")

#define LDMX4(r0, r1, r2, r3, addr) \
    asm volatile("ldmatrix.sync.aligned.m8n8.x4.shared.b16 {%0,%1,%2,%3}, [%4];" \
        : "=r"(r0), "=r"(r1), "=r"(r2), "=r"(r3) : "r"(addr))

__device__ __forceinline__ void mma_f16(float* c, const uint32_t* a, const uint32_t* b) {
    asm volatile(
        "mma.sync.aligned.m16n8k16.row.col.f32.f16.f16.f32 "
        "{%0,%1,%2,%3}, {%4,%5,%6,%7}, {%8,%9}, {%0,%1,%2,%3};"
        : "+f"(c[0]), "+f"(c[1]), "+f"(c[2]), "+f"(c[3])
        : "r"(a[0]), "r"(a[1]), "r"(a[2]), "r"(a[3]), "r"(b[0]), "r"(b[1]));
}

__device__ __forceinline__ float gelu_exact(float v) {
    return 0.5f * v * (1.0f + erff(v * 0.70710678118654752f));
}

// SW128 swizzle on byte offsets (rows are exactly 128B)
#define SWZ(o) ((o) ^ (((o) >> 3) & 0x70))

#define BTILE_B  16384   // B tile: 128 rows x 128B

// ---------------------------------------------------------------------------
// fp16 GEMM: C[M,N] = A[M,K]*B[N,K]^T, fp16 in, f32 accum.
// MTILE x 128 tile (MTILE 128 or 64), Kstage=64, 256 thr, 2-stage cp.async +
// ldmatrix. BIASMODE: 0 none, 1 col bias[n], 2 row bias[m]. OUTHALF: fp16 out.
// ---------------------------------------------------------------------------
template<int MTILE, int BIASMODE, int OUTHALF, int GELU>
__global__ void __launch_bounds__(256, 2)
hgemm(const __half* __restrict__ A, const __half* __restrict__ B,
      const float* __restrict__ bias, void* __restrict__ Cout,
      int N_, int K_, ll sA, ll sB, ll sC) {
    constexpr int ATB = MTILE * 128;          // A tile bytes
    constexpr int BUF = ATB + BTILE_B;        // one stage (A + B)
    constexpr int MT  = MTILE / 32;           // m16 tiles per warp
    constexpr int AJ  = (MTILE * 8) / 256;    // A loader iterations

    extern __shared__ char smraw[];
    A += (ll)blockIdx.z * sA;
    B += (ll)blockIdx.z * sB;
    float*  Cf = (float*) Cout + (OUTHALF ? 0 : (ll)blockIdx.z * sC);
    __half* Ch = (__half*)Cout + (OUTHALF ? (ll)blockIdx.z * sC : 0);

    const int tid = threadIdx.x, lane = tid & 31, wid = tid >> 5;
    const int wm = wid >> 2, wn = wid & 3;
    const int bm = blockIdx.y * MTILE, bn = blockIdx.x << 7;
    const uint32_t sbase = smem_u32(smraw);

    float acc[MT][4][4];
#pragma unroll
    for (int mt = 0; mt < MT; mt++)
#pragma unroll
        for (int nt = 0; nt < 4; nt++)
#pragma unroll
            for (int r = 0; r < 4; r++) acc[mt][nt][r] = 0.0f;

    // loaders: f = tid + j*256: row=f>>3, 16B chunk=f&7 (B uses j<4, A j<AJ)
    int lrow[4], lcc[4];
    uint32_t swo[4];
#pragma unroll
    for (int j = 0; j < 4; j++) {
        int f = tid + (j << 8);
        lrow[j] = f >> 3; lcc[j] = f & 7;
        swo[j] = SWZ((uint32_t)(lrow[j] * 128 + lcc[j] * 16));
    }

    // ldmatrix per-thread address components
    const int l15  = lane & 15;
    const int aklo = (lane >> 4) << 4;
    uint32_t abase[MT], axorm[MT];
#pragma unroll
    for (int mt = 0; mt < MT; mt++) {
        int ar = wm * (MTILE / 2) + mt * 16 + l15;
        abase[mt] = (uint32_t)(ar * 128);
        axorm[mt] = (uint32_t)((ar & 7) << 4);
    }
    const int bg   = lane >> 3;
    const int bsel = bg >> 1;
    const int bklo = (bg & 1) << 4;
    uint32_t bbase[2], bxorm[2];
#pragma unroll
    for (int p = 0; p < 2; p++) {
        int br = wn * 32 + (2 * p + bsel) * 8 + (lane & 7);
        bbase[p] = (uint32_t)(br * 128);
        bxorm[p] = (uint32_t)((br & 7) << 4);
    }

    const int nst = K_ >> 6;

    // prologue: stage 0 into buf 0
#pragma unroll
    for (int j = 0; j < AJ; j++) {
        const __half* ga = A + (size_t)(bm + lrow[j]) * K_ + lcc[j] * 8;
        CP16(sbase + swo[j], ga);
    }
#pragma unroll
    for (int j = 0; j < 4; j++) {
        const __half* gb = B + (size_t)(bn + lrow[j]) * K_ + lcc[j] * 8;
        CP16(sbase + ATB + swo[j], gb);
    }
    CP_COMMIT();

    for (int s = 0; s < nst; s++) {
        CP_WAIT0();
        __syncthreads();

        if (s + 1 < nst) {
            const int k0 = (s + 1) << 6;
            const uint32_t boff = ((s + 1) & 1) * BUF;
#pragma unroll
            for (int j = 0; j < AJ; j++) {
                const __half* ga = A + (size_t)(bm + lrow[j]) * K_ + k0 + lcc[j] * 8;
                CP16(sbase + boff + swo[j], ga);
            }
#pragma unroll
            for (int j = 0; j < 4; j++) {
                const __half* gb = B + (size_t)(bn + lrow[j]) * K_ + k0 + lcc[j] * 8;
                CP16(sbase + boff + ATB + swo[j], gb);
            }
            CP_COMMIT();
        }

        const uint32_t Asm = sbase + (s & 1) * BUF;
        const uint32_t Bsm = Asm + ATB;

#pragma unroll
        for (int kc = 0; kc < 4; kc++) {
            const uint32_t kbb = (uint32_t)(kc << 5);
            uint32_t bf[4][2];
#pragma unroll
            for (int p = 0; p < 2; p++) {
                uint32_t ad = Bsm + bbase[p] + ((kbb + bklo) ^ bxorm[p]);
                LDMX4(bf[2*p][0], bf[2*p][1], bf[2*p+1][0], bf[2*p+1][1], ad);
            }
#pragma unroll
            for (int mt = 0; mt < MT; mt++) {
                uint32_t ad = Asm + abase[mt] + ((kbb + aklo) ^ axorm[mt]);
                uint32_t af[4];
                LDMX4(af[0], af[1], af[2], af[3], ad);
#pragma unroll
                for (int nt = 0; nt < 4; nt++)
                    mma_f16(acc[mt][nt], af, bf[nt]);
            }
        }
    }

    __syncthreads();

    // epilogue
#pragma unroll
    for (int mt = 0; mt < MT; mt++) {
        const int m0 = bm + wm * (MTILE / 2) + mt * 16 + (lane >> 2);
#pragma unroll
        for (int nt = 0; nt < 4; nt++) {
            const int n0 = bn + wn * 32 + nt * 8 + ((lane & 3) << 1);
            float v00 = acc[mt][nt][0], v01 = acc[mt][nt][1];
            float v10 = acc[mt][nt][2], v11 = acc[mt][nt][3];
            if (BIASMODE == 1) {
                float2 bb = *(const float2*)&bias[n0];
                v00 += bb.x; v01 += bb.y; v10 += bb.x; v11 += bb.y;
            } else if (BIASMODE == 2) {
                float r0 = bias[m0], r1 = bias[m0 + 8];
                v00 += r0; v01 += r0; v10 += r1; v11 += r1;
            }
            if (GELU) {
                v00 = gelu_exact(v00); v01 = gelu_exact(v01);
                v10 = gelu_exact(v10); v11 = gelu_exact(v11);
            }
            if (OUTHALF) {
                *(__half2*)&Ch[(size_t)m0 * N_ + n0] =
                    __float22half2_rn(make_float2(v00, v01));
                *(__half2*)&Ch[(size_t)(m0 + 8) * N_ + n0] =
                    __float22half2_rn(make_float2(v10, v11));
            } else {
                *(float2*)&Cf[(size_t)m0 * N_ + n0]       = make_float2(v00, v01);
                *(float2*)&Cf[(size_t)(m0 + 8) * N_ + n0] = make_float2(v10, v11);
            }
        }
    }
}

// ------------------------------------------------------------- aux kernels --
__global__ void pe_kernel(float* __restrict__ pe) {
    int i = blockIdx.x * blockDim.x + threadIdx.x;
    if (i >= S_ * D_) return;
    int s = i / D_, d = i % D_;
    double ang = (double)s * exp(-9.210340371976184 * ((double)d / (double)D_));
    float a = (float)fmod(ang, 6.283185307179586);
    pe[i] = (d & 1) ? cosf(a) : sinf(a);
}

__global__ void embed_kernel(const int* __restrict__ x, const float* __restrict__ emb,
                             const float* __restrict__ pe,
                             float* __restrict__ y, __half* __restrict__ yh) {
    int t = blockIdx.x;
    int s = t & (S_ - 1);
    ll row = x[t];
    const float* er = emb + row * (ll)D_;
    const float* pr = pe + (ll)s * D_;
    float* yr = y + (ll)t * D_;
    __half* yhr = yh + (ll)t * D_;
    for (int p = threadIdx.x; p < D_ / 2; p += blockDim.x) {
        float2 e = *(const float2*)(er + 2 * p);
        float2 q = *(const float2*)(pr + 2 * p);
        float2 v = make_float2(e.x + q.x, e.y + q.y);
        *(float2*)(yr + 2 * p) = v;
        *(__half2*)(yhr + 2 * p) = __float22half2_rn(v);
    }
}

// all-six weight transpose, fused into one launch.
// Each weight has (R/32)*(C/32) = 2304 tiles. grid.x = 6*2304.
struct TransParams {
    const float* in[6];
    __half* out[6];
    int R[6];
    int C[6];
};
__global__ void transpose_all(TransParams P) {
    int w = blockIdx.x / 2304;
    int t = blockIdx.x % 2304;
    const float* in = P.in[w];
    __half* out = P.out[w];
    int R = P.R[w], C = P.C[w];
    int c32 = C >> 5;
    int rb = (t / c32) * 32, cb = (t % c32) * 32;

    __shared__ float tt[32][33];
#pragma unroll
    for (int i = 0; i < 32; i += 8)
        tt[threadIdx.y + i][threadIdx.x] = in[(size_t)(rb + threadIdx.y + i) * C + cb + threadIdx.x];
    __syncthreads();
    int tid = threadIdx.y * 32 + threadIdx.x;
#pragma unroll
    for (int j = 0; j < 2; j++) {
        int pidx = tid + j * 256;
        int c = pidx >> 4, pr = pidx & 15;
        float2 v = make_float2(tt[2 * pr][c], tt[2 * pr + 1][c]);
        *(__half2*)&out[(size_t)(cb + c) * R + rb + 2 * pr] = __float22half2_rn(v);
    }
}

// register-resident softmax: one row (1024) per block, 4 elems/thread
__global__ void softmax_half(const float* __restrict__ s, __half* __restrict__ sp) {
    const float* p = s + (ll)blockIdx.x * S_;
    __half* o = sp + (ll)blockIdx.x * S_;
    __shared__ float red[256];
    const int tid = threadIdx.x;

    float4 v = *(const float4*)(p + tid * 4);

    float m = fmaxf(fmaxf(v.x, v.y), fmaxf(v.z, v.w));
    red[tid] = m; __syncthreads();
    for (int off = 128; off > 0; off >>= 1) {
        if (tid < off) red[tid] = fmaxf(red[tid], red[tid + off]);
        __syncthreads();
    }
    m = red[0]; __syncthreads();

    v.x = expf(v.x - m); v.y = expf(v.y - m);
    v.z = expf(v.z - m); v.w = expf(v.w - m);
    float sum = (v.x + v.y) + (v.z + v.w);
    red[tid] = sum; __syncthreads();
    for (int off = 128; off > 0; off >>= 1) {
        if (tid < off) red[tid] += red[tid + off];
        __syncthreads();
    }
    float inv = 1.0f / red[0];

    __half2 h0 = __float22half2_rn(make_float2(v.x * inv, v.y * inv));
    __half2 h1 = __float22half2_rn(make_float2(v.z * inv, v.w * inv));
    uint2 pack;
    pack.x = *reinterpret_cast<uint32_t*>(&h0);
    pack.y = *reinterpret_cast<uint32_t*>(&h1);
    *(uint2*)(o + tid * 4) = pack;
}

#define LN_CH (S_*D_/128)   // 6144
__global__ void ln_part(const float* __restrict__ a, const float* __restrict__ r,
                        double* __restrict__ part) {
    int b = blockIdx.y, c = blockIdx.x, tid = threadIdx.x;
    size_t base = (size_t)b * (S_*D_) + (size_t)c * LN_CH;
    double s = 0.0, s2 = 0.0;
    for (int i = tid; i < LN_CH; i += 256) {
        float v = a[base + i] + r[base + i];
        s += v; s2 += (double)v * v;
    }
    __shared__ double m1[256], m2[256];
    m1[tid] = s; m2[tid] = s2; __syncthreads();
    for (int o = 128; o > 0; o >>= 1) {
        if (tid < o) { m1[tid] += m1[tid + o]; m2[tid] += m2[tid + o]; }
        __syncthreads();
    }
    if (tid == 0) { part[(b * 128 + c) * 2] = m1[0]; part[(b * 128 + c) * 2 + 1] = m2[0]; }
}
__global__ void ln_stats(const double* __restrict__ part, double* __restrict__ stats) {
    int b = blockIdx.x, tid = threadIdx.x;
    __shared__ double m1[128], m2[128];
    m1[tid] = part[(b * 128 + tid) * 2];
    m2[tid] = part[(b * 128 + tid) * 2 + 1];
    __syncthreads();
    for (int o = 64; o > 0; o >>= 1) {
        if (tid < o) { m1[tid] += m1[tid + o]; m2[tid] += m2[tid + o]; }
        __syncthreads();
    }
    if (tid == 0) {
        double mean = m1[0] / (S_*D_);
        double var  = m2[0] / (S_*D_) - mean * mean;
        stats[b * 2] = mean;
        stats[b * 2 + 1] = 1.0 / sqrt(var + 1e-5);
    }
}
template<int HALFOUT>
__global__ void ln_apply(const float* __restrict__ a, const float* __restrict__ r,
                         const float* __restrict__ w, const float* __restrict__ bb,
                         const double* __restrict__ stats,
                         float* __restrict__ out, __half* __restrict__ oh) {
    int b = blockIdx.y, c = blockIdx.x, tid = threadIdx.x;
    size_t base = (size_t)b * (S_*D_) + (size_t)c * LN_CH;
    size_t sl = (size_t)c * LN_CH;
    float mean = (float)stats[b * 2];
    float rstd = (float)stats[b * 2 + 1];
    for (int i = tid; i < LN_CH / 2; i += 256) {
        float2 av_ = *(const float2*)(a + base + 2 * i);
        float2 rv  = *(const float2*)(r + base + 2 * i);
        float2 wv  = *(const float2*)(w + sl + 2 * i);
        float2 bv  = *(const float2*)(bb + sl + 2 * i);
        float2 v;
        v.x = (av_.x + rv.x - mean) * rstd * wv.x + bv.x;
        v.y = (av_.y + rv.y - mean) * rstd * wv.y + bv.y;
        *(float2*)(out + base + 2 * i) = v;
        if (HALFOUT) *(__half2*)(oh + base + 2 * i) = __float22half2_rn(v);
    }
}

// ------------------------------------------------------------------ launch --
extern "C" void kernel_launch(void* const* d_in, const int* in_sizes, int n_in,
                              void* d_out, int out_size) {
    const int*   x    = (const int*)  d_in[0];
    const float* emb  = (const float*)d_in[1];
    const float* Wq   = (const float*)d_in[2];
    const float* bq   = (const float*)d_in[3];
    const float* Wk   = (const float*)d_in[4];
    const float* bk   = (const float*)d_in[5];
    const float* Wv   = (const float*)d_in[6];
    const float* bv   = (const float*)d_in[7];
    const float* Wo   = (const float*)d_in[8];
    const float* bo   = (const float*)d_in[9];
    const float* W1   = (const float*)d_in[10];
    const float* b1   = (const float*)d_in[11];
    const float* W2   = (const float*)d_in[12];
    const float* b2   = (const float*)d_in[13];
    const float* ln1w = (const float*)d_in[14];
    const float* ln1b = (const float*)d_in[15];
    const float* ln2w = (const float*)d_in[16];
    const float* ln2b = (const float*)d_in[17];
    float* out = (float*)d_out;

    float *pe, *y, *s, *ao, *y1, *f;
    __half *yh, *y1h, *qh, *kh, *vTh, *sh, *avh, *h1h;
    __half *wqt, *wkt, *wvt, *wot, *w1t, *w2t;
    double *part, *stats;
    cudaGetSymbolAddress((void**)&pe,   g_pe);
    cudaGetSymbolAddress((void**)&y,    g_y);
    cudaGetSymbolAddress((void**)&s,    g_s);
    cudaGetSymbolAddress((void**)&ao,   g_ao);
    cudaGetSymbolAddress((void**)&y1,   g_y1);
    cudaGetSymbolAddress((void**)&f,    g_f);
    cudaGetSymbolAddress((void**)&yh,   g_yh);
    cudaGetSymbolAddress((void**)&y1h,  g_y1h);
    cudaGetSymbolAddress((void**)&qh,   g_qh);
    cudaGetSymbolAddress((void**)&kh,   g_kh);
    cudaGetSymbolAddress((void**)&vTh,  g_vTh);
    cudaGetSymbolAddress((void**)&sh,   g_sh);
    cudaGetSymbolAddress((void**)&avh,  g_avh);
    cudaGetSymbolAddress((void**)&h1h,  g_h1h);
    cudaGetSymbolAddress((void**)&wqt,  g_wqt);
    cudaGetSymbolAddress((void**)&wkt,  g_wkt);
    cudaGetSymbolAddress((void**)&wvt,  g_wvt);
    cudaGetSymbolAddress((void**)&wot,  g_wot);
    cudaGetSymbolAddress((void**)&w1t,  g_w1t);
    cudaGetSymbolAddress((void**)&w2t,  g_w2t);
    cudaGetSymbolAddress((void**)&part,  g_part);
    cudaGetSymbolAddress((void**)&stats, g_stats);

    const int SM128 = 2 * (128 * 128 + BTILE_B);   // 65536
    const int SM64  = 2 * (64  * 128 + BTILE_B);   // 49152
    cudaFuncSetAttribute(hgemm<128,1,1,0>, cudaFuncAttributeMaxDynamicSharedMemorySize, SM128);
    cudaFuncSetAttribute(hgemm<128,2,1,0>, cudaFuncAttributeMaxDynamicSharedMemorySize, SM128);
    cudaFuncSetAttribute(hgemm<128,0,0,0>, cudaFuncAttributeMaxDynamicSharedMemorySize, SM128);
    cudaFuncSetAttribute(hgemm<128,0,1,0>, cudaFuncAttributeMaxDynamicSharedMemorySize, SM128);
    cudaFuncSetAttribute(hgemm<64,1,0,0>,  cudaFuncAttributeMaxDynamicSharedMemorySize, SM64);
    cudaFuncSetAttribute(hgemm<64,1,0,1>,  cudaFuncAttributeMaxDynamicSharedMemorySize, SM64);

    // 0. all weights -> transposed fp16, one launch
    TransParams tp;
    tp.in[0] = Wq; tp.out[0] = wqt; tp.R[0] = D_; tp.C[0] = H_;
    tp.in[1] = Wk; tp.out[1] = wkt; tp.R[1] = D_; tp.C[1] = H_;
    tp.in[2] = Wv; tp.out[2] = wvt; tp.R[2] = D_; tp.C[2] = H_;
    tp.in[3] = Wo; tp.out[3] = wot; tp.R[3] = H_; tp.C[3] = D_;
    tp.in[4] = W1; tp.out[4] = w1t; tp.R[4] = D_; tp.C[4] = H_;
    tp.in[5] = W2; tp.out[5] = w2t; tp.R[5] = H_; tp.C[5] = D_;
    transpose_all<<<6 * 2304, dim3(32, 8)>>>(tp);

    // 1. embedding + PE (fp32 + fp16)
    pe_kernel<<<(S_*D_ + 255)/256, 256>>>(pe);
    embed_kernel<<<T_, 256>>>(x, emb, pe, y, yh);

    // 2. q,k  (M=T, N=H, K=D) fp16 out
    hgemm<128,1,1,0><<<dim3(H_/128, T_/128), 256, SM128>>>(yh, wqt, bq, qh, H_, D_, 0, 0, 0);
    hgemm<128,1,1,0><<<dim3(H_/128, T_/128), 256, SM128>>>(yh, wkt, bk, kh, H_, D_, 0, 0, 0);

    // 3. vT_b = wvt @ y_b^T + bv(row)  (M=H, N=S, K=D) fp16 out
    hgemm<128,2,1,0><<<dim3(S_/128, H_/128, B_), 256, SM128>>>(
        wvt, yh, bv, vTh, S_, D_, 0, (ll)S_*D_, (ll)H_*S_);

    // 4. scores_b = q_b @ k_b^T  (M=N=S, K=H) fp32 out
    hgemm<128,0,0,0><<<dim3(S_/128, S_/128, B_), 256, SM128>>>(
        qh, kh, nullptr, s, S_, H_, (ll)S_*H_, (ll)S_*H_, (ll)S_*S_);

    // 5. softmax -> fp16 probs (register-resident)
    softmax_half<<<B_*S_, 256>>>(s, sh);

    // 6. av_b = attn_b @ vT_b^T  (M=S, N=H, K=S) fp16 out
    hgemm<128,0,1,0><<<dim3(H_/128, S_/128, B_), 256, SM128>>>(
        sh, vTh, nullptr, avh, H_, S_, (ll)S_*S_, (ll)H_*S_, (ll)S_*H_);

    // 7. ao = av @ wot^T + bo  (M=T, N=D, K=H) fp32 out, MTILE=64 (wave fix)
    hgemm<64,1,0,0><<<dim3(D_/128, T_/64), 256, SM64>>>(avh, wot, bo, ao, D_, H_, 0, 0, 0);

    // 8. LN1: y1 = LN(y + ao)  (fp32 + fp16)
    ln_part <<<dim3(128, B_), 256>>>(y, ao, part);
    ln_stats<<<B_, 128>>>(part, stats);
    ln_apply<1><<<dim3(128, B_), 256>>>(y, ao, ln1w, ln1b, stats, y1, y1h);

    // 9. FFN: h1 = y1@W1+b1 (fp16);  f = gelu(h1@W2+b2) (fp32), W2 MTILE=64
    hgemm<128,1,1,0><<<dim3(H_/128, T_/128), 256, SM128>>>(y1h, w1t, b1, h1h, H_, D_, 0, 0, 0);
    hgemm<64,1,0,1><<<dim3(D_/128, T_/64), 256, SM64>>>(h1h, w2t, b2, f, D_, H_, 0, 0, 0);

    // 10. LN2 -> out (fp32 only)
    ln_part <<<dim3(128, B_), 256>>>(y1, f, part);
    ln_stats<<<B_, 128>>>(part, stats);
    ln_apply<0><<<dim3(128, B_), 256>>>(y1, f, ln2w, ln2b, stats, out, nullptr);
}

// round 14
// speedup vs baseline: 1.0684x; 1.0684x over previous
#include <cuda_runtime.h>
#include <cuda_fp16.h>
#include <math.h>
#include <cstdint>

#define B_ 8
#define S_ 1024
#define D_ 768
#define H_ 3072
#define T_ (B_*S_)

typedef long long ll;

// ---------------- scratch: fp16 operands -------------------------------------
static __device__ __half g_yh  [T_*D_];
static __device__ __half g_y1h [T_*D_];
static __device__ __half g_qh  [T_*H_];
static __device__ __half g_kh  [T_*H_];
static __device__ __half g_vTh [B_*H_*S_];
static __device__ __half g_sh  [B_*S_*S_];
static __device__ __half g_avh [T_*H_];
static __device__ __half g_h1h [T_*H_];
static __device__ __half g_wqt [H_*D_];
static __device__ __half g_wkt [H_*D_];
static __device__ __half g_wvt [H_*D_];
static __device__ __half g_wot [D_*H_];
static __device__ __half g_w1t [H_*D_];
static __device__ __half g_w2t [D_*H_];
// fp32 scratch
static __device__ float g_pe [S_*D_];
static __device__ float g_y  [T_*D_];
static __device__ float g_s  [B_*S_*S_];
static __device__ float g_ao [T_*D_];
static __device__ float g_y1 [T_*D_];
static __device__ float g_f  [T_*D_];
static __device__ double g_part[B_*128*2];
static __device__ double g_stats[B_*2];

// ------------------------------------------------------------- helpers ------
__device__ __forceinline__ uint32_t smem_u32(const void* p) {
    uint32_t a;
    asm("{ .reg .u64 t; cvta.to.shared.u64 t, %1; cvt.u32.u64 %0, t; }" : "=r"(a) : "l"(p));
    return a;
}
#define CP16(dst, src) \
    asm volatile("cp.async.cg.shared.global [%0], [%1], 16;" :: "r"(dst), "l"(src) : "memory")
#define CP_COMMIT() asm volatile("cp.async.commit_group;" ::: "memory")
#define CP_WAIT0()  asm volatile("cp.async.wait_group 0;" ::: "memory")

#define LDMX4(r0, r1, r2, r3, addr) \
    asm volatile("ldmatrix.sync.aligned.m8n8.x4.shared.b16 {%0,%1,%2,%3}, [%4];" \
        : "=r"(r0), "=r"(r1), "=r"(r2), "=r"(r3) : "r"(addr))

__device__ __forceinline__ void mma_f16(float* c, const uint32_t* a, const uint32_t* b) {
    asm volatile(
        "mma.sync.aligned.m16n8k16.row.col.f32.f16.f16.f32 "
        "{%0,%1,%2,%3}, {%4,%5,%6,%7}, {%8,%9}, {%0,%1,%2,%3};"
        : "+f"(c[0]), "+f"(c[1]), "+f"(c[2]), "+f"(c[3])
        : "r"(a[0]), "r"(a[1]), "r"(a[2]), "r"(a[3]), "r"(b[0]), "r"(b[1]));
}

__device__ __forceinline__ float gelu_exact(float v) {
    return 0.5f * v * (1.0f + erff(v * 0.70710678118654752f));
}

// SW128 swizzle on byte offsets (rows are exactly 128B)
#define SWZ(o) ((o) ^ (((o) >> 3) & 0x70))

// smem tile: 128 rows x 128 B (64 fp16), SW128, K-stage = 64
#define TILE_B   16384
#define BUF_B    (2 * TILE_B)           // A + B
#define SMEM_SZ  (2 * BUF_B)            // double buffer = 65536

// ---------------------------------------------------------------------------
// fp16 GEMM: C[M,N] = A[M,K]*B[N,K]^T, fp16 in, f32 accum.
// 128x128 CTA tile, 128 threads = 4 warps, each warp a 64x64 tile
// (2x fewer smem reads per MMA than 64x32). Kstage=64, 2-stage cp.async.
// BIASMODE: 0 none, 1 col bias[n], 2 row bias[m]. OUTHALF: C fp16 else fp32.
// ---------------------------------------------------------------------------
template<int BIASMODE, int OUTHALF, int GELU>
__global__ void __launch_bounds__(128, 2)
hgemm(const __half* __restrict__ A, const __half* __restrict__ B,
      const float* __restrict__ bias, void* __restrict__ Cout,
      int N_, int K_, ll sA, ll sB, ll sC) {
    extern __shared__ char smraw[];
    A += (ll)blockIdx.z * sA;
    B += (ll)blockIdx.z * sB;
    float*  Cf = (float*) Cout + (OUTHALF ? 0 : (ll)blockIdx.z * sC);
    __half* Ch = (__half*)Cout + (OUTHALF ? (ll)blockIdx.z * sC : 0);

    const int tid = threadIdx.x, lane = tid & 31, wid = tid >> 5;
    const int wm = wid >> 1, wn = wid & 1;        // 2x2 warps, 64x64 each
    const int bm = blockIdx.y << 7, bn = blockIdx.x << 7;
    const uint32_t sbase = smem_u32(smraw);

    float acc[4][8][4];
#pragma unroll
    for (int mt = 0; mt < 4; mt++)
#pragma unroll
        for (int nt = 0; nt < 8; nt++)
#pragma unroll
            for (int r = 0; r < 4; r++) acc[mt][nt][r] = 0.0f;

    // ldmatrix per-thread address components
    const int l15  = lane & 15;
    const int aklo = (lane >> 4) << 4;            // 0 or 16 bytes
    uint32_t abase[4], axorm[4];
#pragma unroll
    for (int mt = 0; mt < 4; mt++) {
        int ar = wm * 64 + mt * 16 + l15;
        abase[mt] = (uint32_t)(ar * 128);
        axorm[mt] = (uint32_t)((ar & 7) << 4);
    }
    const int bg   = lane >> 3;
    const int bsel = bg >> 1;                     // which nt of the pair
    const int bklo = (bg & 1) << 4;
    uint32_t bbase[4], bxorm[4];
#pragma unroll
    for (int p = 0; p < 4; p++) {
        int br = wn * 64 + (2 * p + bsel) * 8 + (lane & 7);
        bbase[p] = (uint32_t)(br * 128);
        bxorm[p] = (uint32_t)((br & 7) << 4);
    }

    const int nst = K_ >> 6;

    // prologue: stage 0 into buf 0 (128 threads x 8 chunks each for A and B)
#pragma unroll
    for (int j = 0; j < 8; j++) {
        int f = tid + (j << 7);
        int row = f >> 3, ch = f & 7;
        uint32_t sw = SWZ((uint32_t)(row * 128 + ch * 16));
        CP16(sbase + sw,          A + (size_t)(bm + row) * K_ + ch * 8);
        CP16(sbase + TILE_B + sw, B + (size_t)(bn + row) * K_ + ch * 8);
    }
    CP_COMMIT();

    for (int s = 0; s < nst; s++) {
        CP_WAIT0();
        __syncthreads();

        if (s + 1 < nst) {
            const int k0 = (s + 1) << 6;
            const uint32_t boff = ((s + 1) & 1) * BUF_B;
#pragma unroll
            for (int j = 0; j < 8; j++) {
                int f = tid + (j << 7);
                int row = f >> 3, ch = f & 7;
                uint32_t sw = SWZ((uint32_t)(row * 128 + ch * 16));
                CP16(sbase + boff + sw,          A + (size_t)(bm + row) * K_ + k0 + ch * 8);
                CP16(sbase + boff + TILE_B + sw, B + (size_t)(bn + row) * K_ + k0 + ch * 8);
            }
            CP_COMMIT();
        }

        const uint32_t Asm = sbase + (s & 1) * BUF_B;
        const uint32_t Bsm = Asm + TILE_B;

#pragma unroll
        for (int kc = 0; kc < 4; kc++) {
            const uint32_t kbb = (uint32_t)(kc << 5);
            uint32_t bf[8][2];
#pragma unroll
            for (int p = 0; p < 4; p++) {
                uint32_t ad = Bsm + bbase[p] + ((kbb + bklo) ^ bxorm[p]);
                LDMX4(bf[2*p][0], bf[2*p][1], bf[2*p+1][0], bf[2*p+1][1], ad);
            }
#pragma unroll
            for (int mt = 0; mt < 4; mt++) {
                uint32_t ad = Asm + abase[mt] + ((kbb + aklo) ^ axorm[mt]);
                uint32_t af[4];
                LDMX4(af[0], af[1], af[2], af[3], ad);
#pragma unroll
                for (int nt = 0; nt < 8; nt++)
                    mma_f16(acc[mt][nt], af, bf[nt]);
            }
        }
    }

    __syncthreads();

    // epilogue
#pragma unroll
    for (int mt = 0; mt < 4; mt++) {
        const int m0 = bm + wm * 64 + mt * 16 + (lane >> 2);
#pragma unroll
        for (int nt = 0; nt < 8; nt++) {
            const int n0 = bn + wn * 64 + nt * 8 + ((lane & 3) << 1);
            float v00 = acc[mt][nt][0], v01 = acc[mt][nt][1];
            float v10 = acc[mt][nt][2], v11 = acc[mt][nt][3];
            if (BIASMODE == 1) {
                float2 bb = *(const float2*)&bias[n0];
                v00 += bb.x; v01 += bb.y; v10 += bb.x; v11 += bb.y;
            } else if (BIASMODE == 2) {
                float r0 = bias[m0], r1 = bias[m0 + 8];
                v00 += r0; v01 += r0; v10 += r1; v11 += r1;
            }
            if (GELU) {
                v00 = gelu_exact(v00); v01 = gelu_exact(v01);
                v10 = gelu_exact(v10); v11 = gelu_exact(v11);
            }
            if (OUTHALF) {
                *(__half2*)&Ch[(size_t)m0 * N_ + n0] =
                    __float22half2_rn(make_float2(v00, v01));
                *(__half2*)&Ch[(size_t)(m0 + 8) * N_ + n0] =
                    __float22half2_rn(make_float2(v10, v11));
            } else {
                *(float2*)&Cf[(size_t)m0 * N_ + n0]       = make_float2(v00, v01);
                *(float2*)&Cf[(size_t)(m0 + 8) * N_ + n0] = make_float2(v10, v11);
            }
        }
    }
}

// ------------------------------------------------------------- aux kernels --
__global__ void pe_kernel(float* __restrict__ pe) {
    int i = blockIdx.x * blockDim.x + threadIdx.x;
    if (i >= S_ * D_) return;
    int s = i / D_, d = i % D_;
    double ang = (double)s * exp(-9.210340371976184 * ((double)d / (double)D_));
    float a = (float)fmod(ang, 6.283185307179586);
    pe[i] = (d & 1) ? cosf(a) : sinf(a);
}

__global__ void embed_kernel(const int* __restrict__ x, const float* __restrict__ emb,
                             const float* __restrict__ pe,
                             float* __restrict__ y, __half* __restrict__ yh) {
    int t = blockIdx.x;
    int s = t & (S_ - 1);
    ll row = x[t];
    const float* er = emb + row * (ll)D_;
    const float* pr = pe + (ll)s * D_;
    float* yr = y + (ll)t * D_;
    __half* yhr = yh + (ll)t * D_;
    for (int p = threadIdx.x; p < D_ / 2; p += blockDim.x) {
        float2 e = *(const float2*)(er + 2 * p);
        float2 q = *(const float2*)(pr + 2 * p);
        float2 v = make_float2(e.x + q.x, e.y + q.y);
        *(float2*)(yr + 2 * p) = v;
        *(__half2*)(yhr + 2 * p) = __float22half2_rn(v);
    }
}

// all-six weight transpose, fused into one launch
struct TransParams {
    const float* in[6];
    __half* out[6];
    int R[6];
    int C[6];
};
__global__ void transpose_all(TransParams P) {
    int w = blockIdx.x / 2304;
    int t = blockIdx.x % 2304;
    const float* in = P.in[w];
    __half* out = P.out[w];
    int R = P.R[w], C = P.C[w];
    int c32 = C >> 5;
    int rb = (t / c32) * 32, cb = (t % c32) * 32;

    __shared__ float tt[32][33];
#pragma unroll
    for (int i = 0; i < 32; i += 8)
        tt[threadIdx.y + i][threadIdx.x] = in[(size_t)(rb + threadIdx.y + i) * C + cb + threadIdx.x];
    __syncthreads();
    int tid = threadIdx.y * 32 + threadIdx.x;
#pragma unroll
    for (int j = 0; j < 2; j++) {
        int pidx = tid + j * 256;
        int c = pidx >> 4, pr = pidx & 15;
        float2 v = make_float2(tt[2 * pr][c], tt[2 * pr + 1][c]);
        *(__half2*)&out[(size_t)(cb + c) * R + rb + 2 * pr] = __float22half2_rn(v);
    }
}

// register-resident softmax: one row (1024) per block, 4 elems/thread
__global__ void softmax_half(const float* __restrict__ s, __half* __restrict__ sp) {
    const float* p = s + (ll)blockIdx.x * S_;
    __half* o = sp + (ll)blockIdx.x * S_;
    __shared__ float red[256];
    const int tid = threadIdx.x;

    float4 v = *(const float4*)(p + tid * 4);

    float m = fmaxf(fmaxf(v.x, v.y), fmaxf(v.z, v.w));
    red[tid] = m; __syncthreads();
    for (int off = 128; off > 0; off >>= 1) {
        if (tid < off) red[tid] = fmaxf(red[tid], red[tid + off]);
        __syncthreads();
    }
    m = red[0]; __syncthreads();

    v.x = expf(v.x - m); v.y = expf(v.y - m);
    v.z = expf(v.z - m); v.w = expf(v.w - m);
    float sum = (v.x + v.y) + (v.z + v.w);
    red[tid] = sum; __syncthreads();
    for (int off = 128; off > 0; off >>= 1) {
        if (tid < off) red[tid] += red[tid + off];
        __syncthreads();
    }
    float inv = 1.0f / red[0];

    __half2 h0 = __float22half2_rn(make_float2(v.x * inv, v.y * inv));
    __half2 h1 = __float22half2_rn(make_float2(v.z * inv, v.w * inv));
    uint2 pack;
    pack.x = *reinterpret_cast<uint32_t*>(&h0);
    pack.y = *reinterpret_cast<uint32_t*>(&h1);
    *(uint2*)(o + tid * 4) = pack;
}

#define LN_CH (S_*D_/128)   // 6144
__global__ void ln_part(const float* __restrict__ a, const float* __restrict__ r,
                        double* __restrict__ part) {
    int b = blockIdx.y, c = blockIdx.x, tid = threadIdx.x;
    size_t base = (size_t)b * (S_*D_) + (size_t)c * LN_CH;
    double s = 0.0, s2 = 0.0;
    for (int i = tid; i < LN_CH; i += 256) {
        float v = a[base + i] + r[base + i];
        s += v; s2 += (double)v * v;
    }
    __shared__ double m1[256], m2[256];
    m1[tid] = s; m2[tid] = s2; __syncthreads();
    for (int o = 128; o > 0; o >>= 1) {
        if (tid < o) { m1[tid] += m1[tid + o]; m2[tid] += m2[tid + o]; }
        __syncthreads();
    }
    if (tid == 0) { part[(b * 128 + c) * 2] = m1[0]; part[(b * 128 + c) * 2 + 1] = m2[0]; }
}
__global__ void ln_stats(const double* __restrict__ part, double* __restrict__ stats) {
    int b = blockIdx.x, tid = threadIdx.x;
    __shared__ double m1[128], m2[128];
    m1[tid] = part[(b * 128 + tid) * 2];
    m2[tid] = part[(b * 128 + tid) * 2 + 1];
    __syncthreads();
    for (int o = 64; o > 0; o >>= 1) {
        if (tid < o) { m1[tid] += m1[tid + o]; m2[tid] += m2[tid + o]; }
        __syncthreads();
    }
    if (tid == 0) {
        double mean = m1[0] / (S_*D_);
        double var  = m2[0] / (S_*D_) - mean * mean;
        stats[b * 2] = mean;
        stats[b * 2 + 1] = 1.0 / sqrt(var + 1e-5);
    }
}
template<int HALFOUT>
__global__ void ln_apply(const float* __restrict__ a, const float* __restrict__ r,
                         const float* __restrict__ w, const float* __restrict__ bb,
                         const double* __restrict__ stats,
                         float* __restrict__ out, __half* __restrict__ oh) {
    int b = blockIdx.y, c = blockIdx.x, tid = threadIdx.x;
    size_t base = (size_t)b * (S_*D_) + (size_t)c * LN_CH;
    size_t sl = (size_t)c * LN_CH;
    float mean = (float)stats[b * 2];
    float rstd = (float)stats[b * 2 + 1];
    for (int i = tid; i < LN_CH / 2; i += 256) {
        float2 av_ = *(const float2*)(a + base + 2 * i);
        float2 rv  = *(const float2*)(r + base + 2 * i);
        float2 wv  = *(const float2*)(w + sl + 2 * i);
        float2 bv  = *(const float2*)(bb + sl + 2 * i);
        float2 v;
        v.x = (av_.x + rv.x - mean) * rstd * wv.x + bv.x;
        v.y = (av_.y + rv.y - mean) * rstd * wv.y + bv.y;
        *(float2*)(out + base + 2 * i) = v;
        if (HALFOUT) *(__half2*)(oh + base + 2 * i) = __float22half2_rn(v);
    }
}

// ------------------------------------------------------------------ launch --
extern "C" void kernel_launch(void* const* d_in, const int* in_sizes, int n_in,
                              void* d_out, int out_size) {
    const int*   x    = (const int*)  d_in[0];
    const float* emb  = (const float*)d_in[1];
    const float* Wq   = (const float*)d_in[2];
    const float* bq   = (const float*)d_in[3];
    const float* Wk   = (const float*)d_in[4];
    const float* bk   = (const float*)d_in[5];
    const float* Wv   = (const float*)d_in[6];
    const float* bv   = (const float*)d_in[7];
    const float* Wo   = (const float*)d_in[8];
    const float* bo   = (const float*)d_in[9];
    const float* W1   = (const float*)d_in[10];
    const float* b1   = (const float*)d_in[11];
    const float* W2   = (const float*)d_in[12];
    const float* b2   = (const float*)d_in[13];
    const float* ln1w = (const float*)d_in[14];
    const float* ln1b = (const float*)d_in[15];
    const float* ln2w = (const float*)d_in[16];
    const float* ln2b = (const float*)d_in[17];
    float* out = (float*)d_out;

    float *pe, *y, *s, *ao, *y1, *f;
    __half *yh, *y1h, *qh, *kh, *vTh, *sh, *avh, *h1h;
    __half *wqt, *wkt, *wvt, *wot, *w1t, *w2t;
    double *part, *stats;
    cudaGetSymbolAddress((void**)&pe,   g_pe);
    cudaGetSymbolAddress((void**)&y,    g_y);
    cudaGetSymbolAddress((void**)&s,    g_s);
    cudaGetSymbolAddress((void**)&ao,   g_ao);
    cudaGetSymbolAddress((void**)&y1,   g_y1);
    cudaGetSymbolAddress((void**)&f,    g_f);
    cudaGetSymbolAddress((void**)&yh,   g_yh);
    cudaGetSymbolAddress((void**)&y1h,  g_y1h);
    cudaGetSymbolAddress((void**)&qh,   g_qh);
    cudaGetSymbolAddress((void**)&kh,   g_kh);
    cudaGetSymbolAddress((void**)&vTh,  g_vTh);
    cudaGetSymbolAddress((void**)&sh,   g_sh);
    cudaGetSymbolAddress((void**)&avh,  g_avh);
    cudaGetSymbolAddress((void**)&h1h,  g_h1h);
    cudaGetSymbolAddress((void**)&wqt,  g_wqt);
    cudaGetSymbolAddress((void**)&wkt,  g_wkt);
    cudaGetSymbolAddress((void**)&wvt,  g_wvt);
    cudaGetSymbolAddress((void**)&wot,  g_wot);
    cudaGetSymbolAddress((void**)&w1t,  g_w1t);
    cudaGetSymbolAddress((void**)&w2t,  g_w2t);
    cudaGetSymbolAddress((void**)&part,  g_part);
    cudaGetSymbolAddress((void**)&stats, g_stats);

    cudaFuncSetAttribute(hgemm<1,1,0>, cudaFuncAttributeMaxDynamicSharedMemorySize, SMEM_SZ);
    cudaFuncSetAttribute(hgemm<2,1,0>, cudaFuncAttributeMaxDynamicSharedMemorySize, SMEM_SZ);
    cudaFuncSetAttribute(hgemm<0,0,0>, cudaFuncAttributeMaxDynamicSharedMemorySize, SMEM_SZ);
    cudaFuncSetAttribute(hgemm<0,1,0>, cudaFuncAttributeMaxDynamicSharedMemorySize, SMEM_SZ);
    cudaFuncSetAttribute(hgemm<1,0,0>, cudaFuncAttributeMaxDynamicSharedMemorySize, SMEM_SZ);
    cudaFuncSetAttribute(hgemm<1,0,1>, cudaFuncAttributeMaxDynamicSharedMemorySize, SMEM_SZ);

    // 0. all weights -> transposed fp16, one launch
    TransParams tp;
    tp.in[0] = Wq; tp.out[0] = wqt; tp.R[0] = D_; tp.C[0] = H_;
    tp.in[1] = Wk; tp.out[1] = wkt; tp.R[1] = D_; tp.C[1] = H_;
    tp.in[2] = Wv; tp.out[2] = wvt; tp.R[2] = D_; tp.C[2] = H_;
    tp.in[3] = Wo; tp.out[3] = wot; tp.R[3] = H_; tp.C[3] = D_;
    tp.in[4] = W1; tp.out[4] = w1t; tp.R[4] = D_; tp.C[4] = H_;
    tp.in[5] = W2; tp.out[5] = w2t; tp.R[5] = H_; tp.C[5] = D_;
    transpose_all<<<6 * 2304, dim3(32, 8)>>>(tp);

    // 1. embedding + PE (fp32 + fp16)
    pe_kernel<<<(S_*D_ + 255)/256, 256>>>(pe);
    embed_kernel<<<T_, 256>>>(x, emb, pe, y, yh);

    // 2. q,k  (M=T, N=H, K=D) fp16 out
    hgemm<1,1,0><<<dim3(H_/128, T_/128), 128, SMEM_SZ>>>(yh, wqt, bq, qh, H_, D_, 0, 0, 0);
    hgemm<1,1,0><<<dim3(H_/128, T_/128), 128, SMEM_SZ>>>(yh, wkt, bk, kh, H_, D_, 0, 0, 0);

    // 3. vT_b = wvt @ y_b^T + bv(row)  (M=H, N=S, K=D) fp16 out
    hgemm<2,1,0><<<dim3(S_/128, H_/128, B_), 128, SMEM_SZ>>>(
        wvt, yh, bv, vTh, S_, D_, 0, (ll)S_*D_, (ll)H_*S_);

    // 4. scores_b = q_b @ k_b^T  (M=N=S, K=H) fp32 out
    hgemm<0,0,0><<<dim3(S_/128, S_/128, B_), 128, SMEM_SZ>>>(
        qh, kh, nullptr, s, S_, H_, (ll)S_*H_, (ll)S_*H_, (ll)S_*S_);

    // 5. softmax -> fp16 probs (register-resident)
    softmax_half<<<B_*S_, 256>>>(s, sh);

    // 6. av_b = attn_b @ vT_b^T  (M=S, N=H, K=S) fp16 out
    hgemm<0,1,0><<<dim3(H_/128, S_/128, B_), 128, SMEM_SZ>>>(
        sh, vTh, nullptr, avh, H_, S_, (ll)S_*S_, (ll)H_*S_, (ll)S_*H_);

    // 7. ao = av @ wot^T + bo  (M=T, N=D, K=H) fp32 out
    hgemm<1,0,0><<<dim3(D_/128, T_/128), 128, SMEM_SZ>>>(avh, wot, bo, ao, D_, H_, 0, 0, 0);

    // 8. LN1: y1 = LN(y + ao)  (fp32 + fp16)
    ln_part <<<dim3(128, B_), 256>>>(y, ao, part);
    ln_stats<<<B_, 128>>>(part, stats);
    ln_apply<1><<<dim3(128, B_), 256>>>(y, ao, ln1w, ln1b, stats, y1, y1h);

    // 9. FFN: h1 = y1@W1+b1 (fp16);  f = gelu(h1@W2+b2) (fp32)
    hgemm<1,1,0><<<dim3(H_/128, T_/128), 128, SMEM_SZ>>>(y1h, w1t, b1, h1h, H_, D_, 0, 0, 0);
    hgemm<1,0,1><<<dim3(D_/128, T_/128), 128, SMEM_SZ>>>(h1h, w2t, b2, f, D_, H_, 0, 0, 0);

    // 10. LN2 -> out (fp32 only)
    ln_part <<<dim3(128, B_), 256>>>(y1, f, part);
    ln_stats<<<B_, 128>>>(part, stats);
    ln_apply<0><<<dim3(128, B_), 256>>>(y1, f, ln2w, ln2b, stats, out, nullptr);
}

// round 15
// speedup vs baseline: 1.0794x; 1.0103x over previous
#include <cuda_runtime.h>
#include <cuda_fp16.h>
#include <math.h>
#include <cstdint>

#define B_ 8
#define S_ 1024
#define D_ 768
#define H_ 3072
#define T_ (B_*S_)

typedef long long ll;

// ---------------- scratch: fp16 operands -------------------------------------
static __device__ __half g_yh  [T_*D_];
static __device__ __half g_y1h [T_*D_];
static __device__ __half g_qkh [T_*2*H_];     // [T][2H]: q | k
static __device__ __half g_vTh [B_*H_*S_];
static __device__ __half g_sh  [B_*S_*S_];
static __device__ __half g_avh [T_*H_];
static __device__ __half g_h1h [T_*H_];
static __device__ __half g_wqkt[2*H_*D_];     // rows 0..H-1 = WqT, H..2H-1 = WkT
static __device__ __half g_wvt [H_*D_];
static __device__ __half g_wot [D_*H_];
static __device__ __half g_w1t [H_*D_];
static __device__ __half g_w2t [D_*H_];
static __device__ float  g_bqk [2*H_];
// fp32 scratch
static __device__ double g_freq[D_];
static __device__ float g_pe [S_*D_];
static __device__ float g_y  [T_*D_];
static __device__ float g_s  [B_*S_*S_];
static __device__ float g_ao [T_*D_];
static __device__ float g_y1 [T_*D_];
static __device__ float g_f  [T_*D_];
static __device__ double g_part[B_*128*2];

// ------------------------------------------------------------- helpers ------
__device__ __forceinline__ uint32_t smem_u32(const void* p) {
    uint32_t a;
    asm("{ .reg .u64 t; cvta.to.shared.u64 t, %1; cvt.u32.u64 %0, t; }" : "=r"(a) : "l"(p));
    return a;
}
#define CP16(dst, src) \
    asm volatile("cp.async.cg.shared.global [%0], [%1], 16;" :: "r"(dst), "l"(src) : "memory")
#define CP_COMMIT() asm volatile("cp.async.commit_group;" ::: "memory")
#define CP_WAIT0()  asm volatile("cp.async.wait_group 0;" ::: "memory")

#define LDMX4(r0, r1, r2, r3, addr) \
    asm volatile("ldmatrix.sync.aligned.m8n8.x4.shared.b16 {%0,%1,%2,%3}, [%4];" \
        : "=r"(r0), "=r"(r1), "=r"(r2), "=r"(r3) : "r"(addr))

__device__ __forceinline__ void mma_f16(float* c, const uint32_t* a, const uint32_t* b) {
    asm volatile(
        "mma.sync.aligned.m16n8k16.row.col.f32.f16.f16.f32 "
        "{%0,%1,%2,%3}, {%4,%5,%6,%7}, {%8,%9}, {%0,%1,%2,%3};"
        : "+f"(c[0]), "+f"(c[1]), "+f"(c[2]), "+f"(c[3])
        : "r"(a[0]), "r"(a[1]), "r"(a[2]), "r"(a[3]), "r"(b[0]), "r"(b[1]));
}

__device__ __forceinline__ float gelu_exact(float v) {
    return 0.5f * v * (1.0f + erff(v * 0.70710678118654752f));
}

// SW128 swizzle on byte offsets (rows are exactly 128B)
#define SWZ(o) ((o) ^ (((o) >> 3) & 0x70))

// smem tile: 128 rows x 128 B (64 fp16), SW128, K-stage = 64
#define TILE_B   16384
#define BUF_B    (2 * TILE_B)           // A + B
#define SMEM_SZ  (2 * BUF_B)            // double buffer = 65536

// ---------------------------------------------------------------------------
// fp16 GEMM: C[.,.] = A*B^T (+bias)(+gelu), fp16 in, f32 accum.
// A rows stride lda, B rows stride ldb, C rows stride ldc (runtime).
// 128x128 CTA tile, 128 thr = 4 warps of 64x64. Kstage=64, 2-stage cp.async.
// BIASMODE: 0 none, 1 col bias[n], 2 row bias[m]. OUTHALF: C fp16 else fp32.
// ---------------------------------------------------------------------------
template<int BIASMODE, int OUTHALF, int GELU>
__global__ void __launch_bounds__(128, 2)
hgemm(const __half* __restrict__ A, const __half* __restrict__ B,
      const float* __restrict__ bias, void* __restrict__ Cout,
      int lda, int ldb, int ldc, int K_, ll sA, ll sB, ll sC) {
    extern __shared__ char smraw[];
    A += (ll)blockIdx.z * sA;
    B += (ll)blockIdx.z * sB;
    float*  Cf = (float*) Cout + (OUTHALF ? 0 : (ll)blockIdx.z * sC);
    __half* Ch = (__half*)Cout + (OUTHALF ? (ll)blockIdx.z * sC : 0);

    const int tid = threadIdx.x, lane = tid & 31, wid = tid >> 5;
    const int wm = wid >> 1, wn = wid & 1;        // 2x2 warps, 64x64 each
    const int bm = blockIdx.y << 7, bn = blockIdx.x << 7;
    const uint32_t sbase = smem_u32(smraw);

    float acc[4][8][4];
#pragma unroll
    for (int mt = 0; mt < 4; mt++)
#pragma unroll
        for (int nt = 0; nt < 8; nt++)
#pragma unroll
            for (int r = 0; r < 4; r++) acc[mt][nt][r] = 0.0f;

    // ldmatrix per-thread address components
    const int l15  = lane & 15;
    const int aklo = (lane >> 4) << 4;
    uint32_t abase[4], axorm[4];
#pragma unroll
    for (int mt = 0; mt < 4; mt++) {
        int ar = wm * 64 + mt * 16 + l15;
        abase[mt] = (uint32_t)(ar * 128);
        axorm[mt] = (uint32_t)((ar & 7) << 4);
    }
    const int bg   = lane >> 3;
    const int bsel = bg >> 1;
    const int bklo = (bg & 1) << 4;
    uint32_t bbase[4], bxorm[4];
#pragma unroll
    for (int p = 0; p < 4; p++) {
        int br = wn * 64 + (2 * p + bsel) * 8 + (lane & 7);
        bbase[p] = (uint32_t)(br * 128);
        bxorm[p] = (uint32_t)((br & 7) << 4);
    }

    const int nst = K_ >> 6;

    // prologue: stage 0 into buf 0 (128 threads x 8 chunks each for A and B)
#pragma unroll
    for (int j = 0; j < 8; j++) {
        int f = tid + (j << 7);
        int row = f >> 3, ch = f & 7;
        uint32_t sw = SWZ((uint32_t)(row * 128 + ch * 16));
        CP16(sbase + sw,          A + (size_t)(bm + row) * lda + ch * 8);
        CP16(sbase + TILE_B + sw, B + (size_t)(bn + row) * ldb + ch * 8);
    }
    CP_COMMIT();

    for (int s = 0; s < nst; s++) {
        CP_WAIT0();
        __syncthreads();

        if (s + 1 < nst) {
            const int k0 = (s + 1) << 6;
            const uint32_t boff = ((s + 1) & 1) * BUF_B;
#pragma unroll
            for (int j = 0; j < 8; j++) {
                int f = tid + (j << 7);
                int row = f >> 3, ch = f & 7;
                uint32_t sw = SWZ((uint32_t)(row * 128 + ch * 16));
                CP16(sbase + boff + sw,          A + (size_t)(bm + row) * lda + k0 + ch * 8);
                CP16(sbase + boff + TILE_B + sw, B + (size_t)(bn + row) * ldb + k0 + ch * 8);
            }
            CP_COMMIT();
        }

        const uint32_t Asm = sbase + (s & 1) * BUF_B;
        const uint32_t Bsm = Asm + TILE_B;

#pragma unroll
        for (int kc = 0; kc < 4; kc++) {
            const uint32_t kbb = (uint32_t)(kc << 5);
            uint32_t bf[8][2];
#pragma unroll
            for (int p = 0; p < 4; p++) {
                uint32_t ad = Bsm + bbase[p] + ((kbb + bklo) ^ bxorm[p]);
                LDMX4(bf[2*p][0], bf[2*p][1], bf[2*p+1][0], bf[2*p+1][1], ad);
            }
#pragma unroll
            for (int mt = 0; mt < 4; mt++) {
                uint32_t ad = Asm + abase[mt] + ((kbb + aklo) ^ axorm[mt]);
                uint32_t af[4];
                LDMX4(af[0], af[1], af[2], af[3], ad);
#pragma unroll
                for (int nt = 0; nt < 8; nt++)
                    mma_f16(acc[mt][nt], af, bf[nt]);
            }
        }
    }

    __syncthreads();

    // epilogue
#pragma unroll
    for (int mt = 0; mt < 4; mt++) {
        const int m0 = bm + wm * 64 + mt * 16 + (lane >> 2);
#pragma unroll
        for (int nt = 0; nt < 8; nt++) {
            const int n0 = bn + wn * 64 + nt * 8 + ((lane & 3) << 1);
            float v00 = acc[mt][nt][0], v01 = acc[mt][nt][1];
            float v10 = acc[mt][nt][2], v11 = acc[mt][nt][3];
            if (BIASMODE == 1) {
                float2 bb = *(const float2*)&bias[n0];
                v00 += bb.x; v01 += bb.y; v10 += bb.x; v11 += bb.y;
            } else if (BIASMODE == 2) {
                float r0 = bias[m0], r1 = bias[m0 + 8];
                v00 += r0; v01 += r0; v10 += r1; v11 += r1;
            }
            if (GELU) {
                v00 = gelu_exact(v00); v01 = gelu_exact(v01);
                v10 = gelu_exact(v10); v11 = gelu_exact(v11);
            }
            if (OUTHALF) {
                *(__half2*)&Ch[(size_t)m0 * ldc + n0] =
                    __float22half2_rn(make_float2(v00, v01));
                *(__half2*)&Ch[(size_t)(m0 + 8) * ldc + n0] =
                    __float22half2_rn(make_float2(v10, v11));
            } else {
                *(float2*)&Cf[(size_t)m0 * ldc + n0]       = make_float2(v00, v01);
                *(float2*)&Cf[(size_t)(m0 + 8) * ldc + n0] = make_float2(v10, v11);
            }
        }
    }
}

// ------------------------------------------------------------- aux kernels --
__global__ void freq_kernel(double* __restrict__ fr) {
    int d = blockIdx.x * blockDim.x + threadIdx.x;
    if (d < D_) fr[d] = exp(-9.210340371976184 * ((double)d / (double)D_));
}

__global__ void pe_kernel(const double* __restrict__ fr, float* __restrict__ pe) {
    int i = blockIdx.x * blockDim.x + threadIdx.x;
    if (i >= S_ * D_) return;
    int s = i / D_, d = i % D_;
    double ang = (double)s * fr[d];
    double k = floor(ang * 0.15915494309189535);        // 1/(2pi)
    float a = (float)(ang - k * 6.283185307179586);
    pe[i] = (d & 1) ? cosf(a) : sinf(a);
}

__global__ void bqk_concat(const float* __restrict__ bq, const float* __restrict__ bk,
                           float* __restrict__ bqk) {
    int i = blockIdx.x * blockDim.x + threadIdx.x;
    if (i < H_) bqk[i] = bq[i];
    else if (i < 2 * H_) bqk[i] = bk[i - H_];
}

__global__ void embed_kernel(const int* __restrict__ x, const float* __restrict__ emb,
                             const float* __restrict__ pe,
                             float* __restrict__ y, __half* __restrict__ yh) {
    int t = blockIdx.x;
    int s = t & (S_ - 1);
    ll row = x[t];
    const float* er = emb + row * (ll)D_;
    const float* pr = pe + (ll)s * D_;
    float* yr = y + (ll)t * D_;
    __half* yhr = yh + (ll)t * D_;
    for (int p = threadIdx.x; p < D_ / 2; p += blockDim.x) {
        float2 e = *(const float2*)(er + 2 * p);
        float2 q = *(const float2*)(pr + 2 * p);
        float2 v = make_float2(e.x + q.x, e.y + q.y);
        *(float2*)(yr + 2 * p) = v;
        *(__half2*)(yhr + 2 * p) = __float22half2_rn(v);
    }
}

// all-six weight transpose, fused into one launch
struct TransParams {
    const float* in[6];
    __half* out[6];
    int R[6];
    int C[6];
};
__global__ void transpose_all(TransParams P) {
    int w = blockIdx.x / 2304;
    int t = blockIdx.x % 2304;
    const float* in = P.in[w];
    __half* out = P.out[w];
    int R = P.R[w], C = P.C[w];
    int c32 = C >> 5;
    int rb = (t / c32) * 32, cb = (t % c32) * 32;

    __shared__ float tt[32][33];
#pragma unroll
    for (int i = 0; i < 32; i += 8)
        tt[threadIdx.y + i][threadIdx.x] = in[(size_t)(rb + threadIdx.y + i) * C + cb + threadIdx.x];
    __syncthreads();
    int tid = threadIdx.y * 32 + threadIdx.x;
#pragma unroll
    for (int j = 0; j < 2; j++) {
        int pidx = tid + j * 256;
        int c = pidx >> 4, pr = pidx & 15;
        float2 v = make_float2(tt[2 * pr][c], tt[2 * pr + 1][c]);
        *(__half2*)&out[(size_t)(cb + c) * R + rb + 2 * pr] = __float22half2_rn(v);
    }
}

// register-resident softmax: one row (1024) per block, 4 elems/thread
__global__ void softmax_half(const float* __restrict__ s, __half* __restrict__ sp) {
    const float* p = s + (ll)blockIdx.x * S_;
    __half* o = sp + (ll)blockIdx.x * S_;
    __shared__ float red[256];
    const int tid = threadIdx.x;

    float4 v = *(const float4*)(p + tid * 4);

    float m = fmaxf(fmaxf(v.x, v.y), fmaxf(v.z, v.w));
    red[tid] = m; __syncthreads();
    for (int off = 128; off > 0; off >>= 1) {
        if (tid < off) red[tid] = fmaxf(red[tid], red[tid + off]);
        __syncthreads();
    }
    m = red[0]; __syncthreads();

    v.x = expf(v.x - m); v.y = expf(v.y - m);
    v.z = expf(v.z - m); v.w = expf(v.w - m);
    float sum = (v.x + v.y) + (v.z + v.w);
    red[tid] = sum; __syncthreads();
    for (int off = 128; off > 0; off >>= 1) {
        if (tid < off) red[tid] += red[tid + off];
        __syncthreads();
    }
    float inv = 1.0f / red[0];

    __half2 h0 = __float22half2_rn(make_float2(v.x * inv, v.y * inv));
    __half2 h1 = __float22half2_rn(make_float2(v.z * inv, v.w * inv));
    uint2 pack;
    pack.x = *reinterpret_cast<uint32_t*>(&h0);
    pack.y = *reinterpret_cast<uint32_t*>(&h1);
    *(uint2*)(o + tid * 4) = pack;
}

#define LN_CH (S_*D_/128)   // 6144
__global__ void ln_part(const float* __restrict__ a, const float* __restrict__ r,
                        double* __restrict__ part) {
    int b = blockIdx.y, c = blockIdx.x, tid = threadIdx.x;
    size_t base = (size_t)b * (S_*D_) + (size_t)c * LN_CH;
    double s = 0.0, s2 = 0.0;
    for (int i = tid; i < LN_CH; i += 256) {
        float v = a[base + i] + r[base + i];
        s += v; s2 += (double)v * v;
    }
    __shared__ double m1[256], m2[256];
    m1[tid] = s; m2[tid] = s2; __syncthreads();
    for (int o = 128; o > 0; o >>= 1) {
        if (tid < o) { m1[tid] += m1[tid + o]; m2[tid] += m2[tid + o]; }
        __syncthreads();
    }
    if (tid == 0) { part[(b * 128 + c) * 2] = m1[0]; part[(b * 128 + c) * 2 + 1] = m2[0]; }
}

// ln_apply with fused stats reduction (each block redundantly reduces 128 partials)
template<int HALFOUT>
__global__ void ln_apply(const float* __restrict__ a, const float* __restrict__ r,
                         const float* __restrict__ w, const float* __restrict__ bb,
                         const double* __restrict__ part,
                         float* __restrict__ out, __half* __restrict__ oh) {
    int b = blockIdx.y, c = blockIdx.x, tid = threadIdx.x;
    __shared__ double m1[128], m2[128];
    if (tid < 128) {
        m1[tid] = part[(b * 128 + tid) * 2];
        m2[tid] = part[(b * 128 + tid) * 2 + 1];
    }
    __syncthreads();
    for (int o = 64; o > 0; o >>= 1) {
        if (tid < o) { m1[tid] += m1[tid + o]; m2[tid] += m2[tid + o]; }
        __syncthreads();
    }
    double meand = m1[0] / (S_*D_);
    double vard  = m2[0] / (S_*D_) - meand * meand;
    float mean = (float)meand;
    float rstd = (float)(1.0 / sqrt(vard + 1e-5));

    size_t base = (size_t)b * (S_*D_) + (size_t)c * LN_CH;
    size_t sl = (size_t)c * LN_CH;
    for (int i = tid; i < LN_CH / 2; i += 256) {
        float2 av_ = *(const float2*)(a + base + 2 * i);
        float2 rv  = *(const float2*)(r + base + 2 * i);
        float2 wv  = *(const float2*)(w + sl + 2 * i);
        float2 bv  = *(const float2*)(bb + sl + 2 * i);
        float2 v;
        v.x = (av_.x + rv.x - mean) * rstd * wv.x + bv.x;
        v.y = (av_.y + rv.y - mean) * rstd * wv.y + bv.y;
        *(float2*)(out + base + 2 * i) = v;
        if (HALFOUT) *(__half2*)(oh + base + 2 * i) = __float22half2_rn(v);
    }
}

// ------------------------------------------------------------------ launch --
extern "C" void kernel_launch(void* const* d_in, const int* in_sizes, int n_in,
                              void* d_out, int out_size) {
    const int*   x    = (const int*)  d_in[0];
    const float* emb  = (const float*)d_in[1];
    const float* Wq   = (const float*)d_in[2];
    const float* bq   = (const float*)d_in[3];
    const float* Wk   = (const float*)d_in[4];
    const float* bk   = (const float*)d_in[5];
    const float* Wv   = (const float*)d_in[6];
    const float* bv   = (const float*)d_in[7];
    const float* Wo   = (const float*)d_in[8];
    const float* bo   = (const float*)d_in[9];
    const float* W1   = (const float*)d_in[10];
    const float* b1   = (const float*)d_in[11];
    const float* W2   = (const float*)d_in[12];
    const float* b2   = (const float*)d_in[13];
    const float* ln1w = (const float*)d_in[14];
    const float* ln1b = (const float*)d_in[15];
    const float* ln2w = (const float*)d_in[16];
    const float* ln2b = (const float*)d_in[17];
    float* out = (float*)d_out;

    float *pe, *y, *s, *ao, *y1, *f, *bqk;
    double *freq;
    __half *yh, *y1h, *qkh, *vTh, *sh, *avh, *h1h;
    __half *wqkt, *wvt, *wot, *w1t, *w2t;
    double *part;
    cudaGetSymbolAddress((void**)&pe,   g_pe);
    cudaGetSymbolAddress((void**)&y,    g_y);
    cudaGetSymbolAddress((void**)&s,    g_s);
    cudaGetSymbolAddress((void**)&ao,   g_ao);
    cudaGetSymbolAddress((void**)&y1,   g_y1);
    cudaGetSymbolAddress((void**)&f,    g_f);
    cudaGetSymbolAddress((void**)&bqk,  g_bqk);
    cudaGetSymbolAddress((void**)&freq, g_freq);
    cudaGetSymbolAddress((void**)&yh,   g_yh);
    cudaGetSymbolAddress((void**)&y1h,  g_y1h);
    cudaGetSymbolAddress((void**)&qkh,  g_qkh);
    cudaGetSymbolAddress((void**)&vTh,  g_vTh);
    cudaGetSymbolAddress((void**)&sh,   g_sh);
    cudaGetSymbolAddress((void**)&avh,  g_avh);
    cudaGetSymbolAddress((void**)&h1h,  g_h1h);
    cudaGetSymbolAddress((void**)&wqkt, g_wqkt);
    cudaGetSymbolAddress((void**)&wvt,  g_wvt);
    cudaGetSymbolAddress((void**)&wot,  g_wot);
    cudaGetSymbolAddress((void**)&w1t,  g_w1t);
    cudaGetSymbolAddress((void**)&w2t,  g_w2t);
    cudaGetSymbolAddress((void**)&part, g_part);

    cudaFuncSetAttribute(hgemm<1,1,0>, cudaFuncAttributeMaxDynamicSharedMemorySize, SMEM_SZ);
    cudaFuncSetAttribute(hgemm<2,1,0>, cudaFuncAttributeMaxDynamicSharedMemorySize, SMEM_SZ);
    cudaFuncSetAttribute(hgemm<0,0,0>, cudaFuncAttributeMaxDynamicSharedMemorySize, SMEM_SZ);
    cudaFuncSetAttribute(hgemm<0,1,0>, cudaFuncAttributeMaxDynamicSharedMemorySize, SMEM_SZ);
    cudaFuncSetAttribute(hgemm<1,0,0>, cudaFuncAttributeMaxDynamicSharedMemorySize, SMEM_SZ);
    cudaFuncSetAttribute(hgemm<1,0,1>, cudaFuncAttributeMaxDynamicSharedMemorySize, SMEM_SZ);

    // 0. all weights -> transposed fp16, one launch (Wq,Wk into concat buffer)
    TransParams tp;
    tp.in[0] = Wq; tp.out[0] = wqkt;                     tp.R[0] = D_; tp.C[0] = H_;
    tp.in[1] = Wk; tp.out[1] = wqkt + (size_t)H_ * D_;   tp.R[1] = D_; tp.C[1] = H_;
    tp.in[2] = Wv; tp.out[2] = wvt;                      tp.R[2] = D_; tp.C[2] = H_;
    tp.in[3] = Wo; tp.out[3] = wot;                      tp.R[3] = H_; tp.C[3] = D_;
    tp.in[4] = W1; tp.out[4] = w1t;                      tp.R[4] = D_; tp.C[4] = H_;
    tp.in[5] = W2; tp.out[5] = w2t;                      tp.R[5] = H_; tp.C[5] = D_;
    transpose_all<<<6 * 2304, dim3(32, 8)>>>(tp);
    bqk_concat<<<(2*H_ + 255)/256, 256>>>(bq, bk, bqk);

    // 1. embedding + PE (fp32 + fp16)
    freq_kernel<<<3, 256>>>(freq);
    pe_kernel<<<(S_*D_ + 255)/256, 256>>>(freq, pe);
    embed_kernel<<<T_, 256>>>(x, emb, pe, y, yh);

    // 2. fused q|k GEMM: qkh[T][2H] = yh @ wqkt^T + bqk   (K=768)
    hgemm<1,1,0><<<dim3(2*H_/128, T_/128), 128, SMEM_SZ>>>(
        yh, wqkt, bqk, qkh, D_, D_, 2*H_, D_, 0, 0, 0);

    // 3. vT_b = wvt @ y_b^T + bv(row)  (M=H, N=S, K=768) fp16 out
    hgemm<2,1,0><<<dim3(S_/128, H_/128, B_), 128, SMEM_SZ>>>(
        wvt, yh, bv, vTh, D_, D_, S_, D_, 0, (ll)S_*D_, (ll)H_*S_);

    // 4. scores_b = q_b @ k_b^T  (M=N=S, K=H) fp32 out; q,k strided views of qkh
    hgemm<0,0,0><<<dim3(S_/128, S_/128, B_), 128, SMEM_SZ>>>(
        qkh, qkh + H_, nullptr, s, 2*H_, 2*H_, S_, H_,
        (ll)S_*2*H_, (ll)S_*2*H_, (ll)S_*S_);

    // 5. softmax -> fp16 probs (register-resident)
    softmax_half<<<B_*S_, 256>>>(s, sh);

    // 6. av_b = attn_b @ vT_b^T  (M=S, N=H, K=S) fp16 out
    hgemm<0,1,0><<<dim3(H_/128, S_/128, B_), 128, SMEM_SZ>>>(
        sh, vTh, nullptr, avh, S_, S_, H_, S_, (ll)S_*S_, (ll)H_*S_, (ll)S_*H_);

    // 7. ao = av @ wot^T + bo  (M=T, N=D, K=H) fp32 out
    hgemm<1,0,0><<<dim3(D_/128, T_/128), 128, SMEM_SZ>>>(
        avh, wot, bo, ao, H_, H_, D_, H_, 0, 0, 0);

    // 8. LN1: y1 = LN(y + ao)  (fp32 + fp16), stats fused into apply
    ln_part <<<dim3(128, B_), 256>>>(y, ao, part);
    ln_apply<1><<<dim3(128, B_), 256>>>(y, ao, ln1w, ln1b, part, y1, y1h);

    // 9. FFN: h1 = y1@W1+b1 (fp16);  f = gelu(h1@W2+b2) (fp32)
    hgemm<1,1,0><<<dim3(H_/128, T_/128), 128, SMEM_SZ>>>(
        y1h, w1t, b1, h1h, D_, D_, H_, D_, 0, 0, 0);
    hgemm<1,0,1><<<dim3(D_/128, T_/128), 128, SMEM_SZ>>>(
        h1h, w2t, b2, f, H_, H_, D_, H_, 0, 0, 0);

    // 10. LN2 -> out (fp32 only)
    ln_part <<<dim3(128, B_), 256>>>(y1, f, part);
    ln_apply<0><<<dim3(128, B_), 256>>>(y1, f, ln2w, ln2b, part, out, nullptr);
}